// round 7
// baseline (speedup 1.0000x reference)
#include <cuda_runtime.h>
#include <cstdint>

#define CHUNK 1024          // floats per early-exit quantum (4 KB)
#define NSUB  8             // sub-blocks of 128 floats (one float4 per lane)

__device__ int g_row_counter;

__global__ void reset_counter_kernel() { g_row_counter = 0; }

// ---------------------------------------------------------------------------
// Warp-autonomous bidirectional inverse-CDF sampler with speculative prefetch.
//   sample = #{v : r > csum[v]},  csum monotone (p >= 0), sum(p) ~= 1.
// r <= 0.5: forward scan;  r > 0.5: backward scan with q = 1-r.
// Streaming loop keeps loads in flight across the reduce/decide phase by
// issuing chunk c+1 before reducing chunk c. On crossing, the chunk is
// re-read (guaranteed L2 hit) for the ordered in-chunk count.
// One warp per row, rows distributed via global atomic counter. No barriers.
// Output dtype float32 (samples <= 32000 exact in fp32).
// ---------------------------------------------------------------------------
__global__ void __launch_bounds__(256) sampler_kernel(
    const float* __restrict__ p, const float* __restrict__ rng,
    float* __restrict__ out, int V, int rows)
{
    const int lane = threadIdx.x & 31;
    const int nch  = (V + CHUNK - 1) / CHUNK;

    for (;;) {
        int row;
        if (lane == 0) row = atomicAdd(&g_row_counter, 1);
        row = __shfl_sync(0xFFFFFFFFu, row, 0);
        if (row >= rows) return;

        const float r = __ldg(&rng[row]);
        const float* __restrict__ prow = p + (size_t)row * V;
        const bool fwd = (r <= 0.5f);
        const float thr = fwd ? r : (1.0f - r);   // forward: r;  backward: q

        float4 buf[NSUB];

        // ---- issue loads for logical chunk 0 ----
        {
            const int lo = fwd ? 0 : max(0, V - CHUNK);
            const int hi = fwd ? min(V, CHUNK) : V;
            #pragma unroll
            for (int j = 0; j < NSUB; j++) {
                const int idx = lo + j * 128 + lane * 4;
                float4 a = make_float4(0.f, 0.f, 0.f, 0.f);
                if (idx + 4 <= hi) a = *reinterpret_cast<const float4*>(prow + idx);
                else {
                    if (idx + 0 < hi) a.x = prow[idx + 0];
                    if (idx + 1 < hi) a.y = prow[idx + 1];
                    if (idx + 2 < hi) a.z = prow[idx + 2];
                }
                buf[j] = a;
            }
        }

        // ---- streaming loop with speculative prefetch ----
        float acc = 0.0f;        // mass already passed (fwd: prefix; bwd: suffix)
        int   cross = -1;        // logical chunk index containing the crossing

        for (int c = 0; c < nch; c++) {
            // consume current buffer into a lane scalar (waits on loads)
            float s = ((buf[0].x + buf[0].y) + (buf[0].z + buf[0].w))
                    + ((buf[1].x + buf[1].y) + (buf[1].z + buf[1].w))
                    + ((buf[2].x + buf[2].y) + (buf[2].z + buf[2].w))
                    + ((buf[3].x + buf[3].y) + (buf[3].z + buf[3].w))
                    + ((buf[4].x + buf[4].y) + (buf[4].z + buf[4].w))
                    + ((buf[5].x + buf[5].y) + (buf[5].z + buf[5].w))
                    + ((buf[6].x + buf[6].y) + (buf[6].z + buf[6].w))
                    + ((buf[7].x + buf[7].y) + (buf[7].z + buf[7].w));

            // speculatively issue loads for chunk c+1 while we reduce
            if (c + 1 < nch) {
                const int cn = c + 1;
                const int lo = fwd ? cn * CHUNK : max(0, V - (cn + 1) * CHUNK);
                const int hi = fwd ? min(V, (cn + 1) * CHUNK) : (V - cn * CHUNK);
                #pragma unroll
                for (int j = 0; j < NSUB; j++) {
                    const int idx = lo + j * 128 + lane * 4;
                    float4 a = make_float4(0.f, 0.f, 0.f, 0.f);
                    if (idx + 4 <= hi) a = *reinterpret_cast<const float4*>(prow + idx);
                    else {
                        if (idx + 0 < hi) a.x = prow[idx + 0];
                        if (idx + 1 < hi) a.y = prow[idx + 1];
                        if (idx + 2 < hi) a.z = prow[idx + 2];
                    }
                    buf[j] = a;
                }
            }

            // warp reduce + exit decision (overlapped with c+1 loads)
            #pragma unroll
            for (int d = 16; d > 0; d >>= 1)
                s += __shfl_xor_sync(0xFFFFFFFFu, s, d);

            const bool hit = fwd ? (acc + s >= thr) : (acc + s > thr);
            if (hit) { cross = c; break; }
            acc += s;
        }

        // ---- resolve within the crossing chunk (re-read: L2 hit) ----
        float res;
        if (cross < 0) {
            res = fwd ? (float)V : 0.0f;   // unreachable in practice (sum ~ 1)
        } else if (fwd) {
            const int lo = cross * CHUNK;
            const int hi = min(V, lo + CHUNK);
            float carry = acc;
            int cnt = 0;
            #pragma unroll
            for (int j = 0; j < NSUB; j++) {
                const int idx = lo + j * 128 + lane * 4;
                float4 a = make_float4(0.f, 0.f, 0.f, 0.f);
                if (idx + 4 <= hi) a = *reinterpret_cast<const float4*>(prow + idx);
                else {
                    if (idx + 0 < hi) a.x = prow[idx + 0];
                    if (idx + 1 < hi) a.y = prow[idx + 1];
                    if (idx + 2 < hi) a.z = prow[idx + 2];
                }
                const float s4 = (a.x + a.y) + (a.z + a.w);
                float scan = s4;
                #pragma unroll
                for (int d = 1; d < 32; d <<= 1) {
                    float y = __shfl_up_sync(0xFFFFFFFFu, scan, d);
                    if (lane >= d) scan += y;
                }
                const float c0 = carry + (scan - s4) + a.x;
                const float c1 = c0 + a.y;
                const float c2 = c1 + a.z;
                const float c3 = c2 + a.w;
                cnt += (idx + 0 < hi && c0 < thr);
                cnt += (idx + 1 < hi && c1 < thr);
                cnt += (idx + 2 < hi && c2 < thr);
                cnt += (idx + 3 < hi && c3 < thr);
                carry += __shfl_sync(0xFFFFFFFFu, scan, 31);
            }
            #pragma unroll
            for (int d = 16; d > 0; d >>= 1)
                cnt += __shfl_xor_sync(0xFFFFFFFFu, cnt, d);
            res = (float)(lo + cnt);
        } else {
            // backward: count v in [lo,hi) with suf[v] > q; carry = suffix >= hi
            const int hi = V - cross * CHUNK;
            const int lo = max(0, hi - CHUNK);
            float carry = acc;
            int cnt = 0;
            #pragma unroll
            for (int j = NSUB - 1; j >= 0; j--) {
                const int idx = lo + j * 128 + lane * 4;
                float4 a = make_float4(0.f, 0.f, 0.f, 0.f);
                if (idx + 4 <= hi) a = *reinterpret_cast<const float4*>(prow + idx);
                else {
                    if (idx + 0 < hi) a.x = prow[idx + 0];
                    if (idx + 1 < hi) a.y = prow[idx + 1];
                    if (idx + 2 < hi) a.z = prow[idx + 2];
                }
                const float s4 = (a.x + a.y) + (a.z + a.w);
                float rs = s4;                      // reverse inclusive scan
                #pragma unroll
                for (int d = 1; d < 32; d <<= 1) {
                    float y = __shfl_down_sync(0xFFFFFFFFu, rs, d);
                    if (lane < 32 - d) rs += y;
                }
                const float rev_excl = rs - s4;     // lanes above this one
                const float sw = carry + rev_excl + a.w;   // suf[idx+3]
                const float sz = sw + a.z;                 // suf[idx+2]
                const float sy = sz + a.y;                 // suf[idx+1]
                const float sx = sy + a.x;                 // suf[idx]
                cnt += (idx + 3 < hi && sw > thr);
                cnt += (idx + 2 < hi && sz > thr);
                cnt += (idx + 1 < hi && sy > thr);
                cnt += (idx + 0 < hi && sx > thr);
                carry += __shfl_sync(0xFFFFFFFFu, rs, 0);
            }
            #pragma unroll
            for (int d = 16; d > 0; d >>= 1)
                cnt += __shfl_xor_sync(0xFFFFFFFFu, cnt, d);
            res = (float)(lo + cnt - 1 + (acc > thr ? 1 : 0));
        }

        if (lane == 0) out[row] = res;
    }
}

extern "C" void kernel_launch(void* const* d_in, const int* in_sizes, int n_in,
                              void* d_out, int out_size) {
    // Resolve inputs by element count (p is the huge one, rng has `rows`).
    int ip = 0;
    for (int i = 1; i < n_in; i++)
        if (in_sizes[i] > in_sizes[ip]) ip = i;
    const float* p = (const float*)d_in[ip];

    const int rows = out_size;                       // B*T = 8192
    int ir = (ip == 0) ? 1 : 0;
    for (int i = 0; i < n_in; i++)
        if (i != ip && in_sizes[i] == rows) { ir = i; break; }
    const float* rng = (const float*)d_in[ir];

    float* out = (float*)d_out;                      // output dtype: float32

    const long long pelems = (long long)in_sizes[ip];
    const int V = (int)(pelems / rows);              // 32000

    reset_counter_kernel<<<1, 1>>>();
    sampler_kernel<<<1184, 256>>>(p, rng, out, V, rows);
}

// round 8
// speedup vs baseline: 1.0089x; 1.0089x over previous
#include <cuda_runtime.h>
#include <cstdint>

#define CHUNK 1024          // floats per early-exit quantum (4 KB)
#define NSUB  8             // sub-blocks of 128 floats (one float4 per lane)

__device__ int g_row_counter;

__global__ void reset_counter_kernel() { g_row_counter = 0; }

// ---------------------------------------------------------------------------
// Warp-autonomous bidirectional inverse-CDF sampler (low-register variant).
//   sample = #{v : r > csum[v]},  csum monotone (p >= 0), sum(p) ~= 1.
// r <= 0.5: forward scan;  r > 0.5: backward scan with q = 1-r.
// Streaming loop: load 4KB chunk (8 independent float4/lane), reduce into a
// scalar immediately (no retention), exit when the running mass crosses thr.
// The crossing chunk is re-read for the ordered count — guaranteed L2 hit.
// One warp per row, rows distributed via a global atomic counter.
// Output dtype float32 (samples <= 32000 exact in fp32).
// ---------------------------------------------------------------------------
__global__ void __launch_bounds__(256) sampler_kernel(
    const float* __restrict__ p, const float* __restrict__ rng,
    float* __restrict__ out, int V, int rows)
{
    const int lane = threadIdx.x & 31;
    const int nch  = (V + CHUNK - 1) / CHUNK;

    for (;;) {
        int row;
        if (lane == 0) row = atomicAdd(&g_row_counter, 1);
        row = __shfl_sync(0xFFFFFFFFu, row, 0);
        if (row >= rows) return;

        const float r = __ldg(&rng[row]);
        const float* __restrict__ prow = p + (size_t)row * V;
        const bool fwd = (r <= 0.5f);
        const float thr = fwd ? r : (1.0f - r);

        // ---- streaming scan: no data retention beyond the load buffer ----
        float acc = 0.0f;        // mass already passed (fwd: prefix; bwd: suffix)
        int   cross = -1;

        for (int c = 0; c < nch; c++) {
            const int lo = fwd ? c * CHUNK : max(0, V - (c + 1) * CHUNK);
            const int hi = fwd ? min(V, (c + 1) * CHUNK) : (V - c * CHUNK);

            float4 b[NSUB];
            #pragma unroll
            for (int j = 0; j < NSUB; j++) {
                const int idx = lo + j * 128 + lane * 4;
                float4 a = make_float4(0.f, 0.f, 0.f, 0.f);
                if (idx + 4 <= hi) a = *reinterpret_cast<const float4*>(prow + idx);
                else {
                    if (idx + 0 < hi) a.x = prow[idx + 0];
                    if (idx + 1 < hi) a.y = prow[idx + 1];
                    if (idx + 2 < hi) a.z = prow[idx + 2];
                }
                b[j] = a;
            }
            float s = (((b[0].x + b[0].y) + (b[0].z + b[0].w))
                     + ((b[1].x + b[1].y) + (b[1].z + b[1].w)))
                    + (((b[2].x + b[2].y) + (b[2].z + b[2].w))
                     + ((b[3].x + b[3].y) + (b[3].z + b[3].w)))
                    + (((b[4].x + b[4].y) + (b[4].z + b[4].w))
                     + ((b[5].x + b[5].y) + (b[5].z + b[5].w)))
                    + (((b[6].x + b[6].y) + (b[6].z + b[6].w))
                     + ((b[7].x + b[7].y) + (b[7].z + b[7].w)));
            #pragma unroll
            for (int d = 16; d > 0; d >>= 1)
                s += __shfl_xor_sync(0xFFFFFFFFu, s, d);

            const bool hit = fwd ? (acc + s >= thr) : (acc + s > thr);
            if (hit) { cross = c; break; }
            acc += s;
        }

        // ---- resolve inside the crossing chunk (re-read: L2 hit) ----
        float res;
        if (cross < 0) {
            res = fwd ? (float)V : 0.0f;   // unreachable in practice (sum ~1)
        } else if (fwd) {
            const int lo = cross * CHUNK;
            const int hi = min(V, lo + CHUNK);
            float carry = acc;
            int cnt = 0;
            #pragma unroll
            for (int j = 0; j < NSUB; j++) {
                const int idx = lo + j * 128 + lane * 4;
                float4 a = make_float4(0.f, 0.f, 0.f, 0.f);
                if (idx + 4 <= hi) a = *reinterpret_cast<const float4*>(prow + idx);
                else {
                    if (idx + 0 < hi) a.x = prow[idx + 0];
                    if (idx + 1 < hi) a.y = prow[idx + 1];
                    if (idx + 2 < hi) a.z = prow[idx + 2];
                }
                const float s4 = (a.x + a.y) + (a.z + a.w);
                float scan = s4;
                #pragma unroll
                for (int d = 1; d < 32; d <<= 1) {
                    float y = __shfl_up_sync(0xFFFFFFFFu, scan, d);
                    if (lane >= d) scan += y;
                }
                const float c0 = carry + (scan - s4) + a.x;
                const float c1 = c0 + a.y;
                const float c2 = c1 + a.z;
                const float c3 = c2 + a.w;
                cnt += (idx + 0 < hi && c0 < thr);
                cnt += (idx + 1 < hi && c1 < thr);
                cnt += (idx + 2 < hi && c2 < thr);
                cnt += (idx + 3 < hi && c3 < thr);
                carry += __shfl_sync(0xFFFFFFFFu, scan, 31);
            }
            #pragma unroll
            for (int d = 16; d > 0; d >>= 1)
                cnt += __shfl_xor_sync(0xFFFFFFFFu, cnt, d);
            res = (float)(lo + cnt);
        } else {
            // backward: count v in [lo,hi) with suf[v] > q; acc = suffix >= hi
            const int hi = V - cross * CHUNK;
            const int lo = max(0, hi - CHUNK);
            float carry = acc;
            int cnt = 0;
            #pragma unroll
            for (int j = NSUB - 1; j >= 0; j--) {
                const int idx = lo + j * 128 + lane * 4;
                float4 a = make_float4(0.f, 0.f, 0.f, 0.f);
                if (idx + 4 <= hi) a = *reinterpret_cast<const float4*>(prow + idx);
                else {
                    if (idx + 0 < hi) a.x = prow[idx + 0];
                    if (idx + 1 < hi) a.y = prow[idx + 1];
                    if (idx + 2 < hi) a.z = prow[idx + 2];
                }
                const float s4 = (a.x + a.y) + (a.z + a.w);
                float rs = s4;                      // reverse inclusive scan
                #pragma unroll
                for (int d = 1; d < 32; d <<= 1) {
                    float y = __shfl_down_sync(0xFFFFFFFFu, rs, d);
                    if (lane < 32 - d) rs += y;
                }
                const float rev_excl = rs - s4;
                const float sw = carry + rev_excl + a.w;   // suf[idx+3]
                const float sz = sw + a.z;                 // suf[idx+2]
                const float sy = sz + a.y;                 // suf[idx+1]
                const float sx = sy + a.x;                 // suf[idx]
                cnt += (idx + 3 < hi && sw > thr);
                cnt += (idx + 2 < hi && sz > thr);
                cnt += (idx + 1 < hi && sy > thr);
                cnt += (idx + 0 < hi && sx > thr);
                carry += __shfl_sync(0xFFFFFFFFu, rs, 0);
            }
            #pragma unroll
            for (int d = 16; d > 0; d >>= 1)
                cnt += __shfl_xor_sync(0xFFFFFFFFu, cnt, d);
            res = (float)(lo + cnt - 1 + (acc > thr ? 1 : 0));
        }

        if (lane == 0) out[row] = res;
    }
}

extern "C" void kernel_launch(void* const* d_in, const int* in_sizes, int n_in,
                              void* d_out, int out_size) {
    // Resolve inputs by element count (p is the huge one, rng has `rows`).
    int ip = 0;
    for (int i = 1; i < n_in; i++)
        if (in_sizes[i] > in_sizes[ip]) ip = i;
    const float* p = (const float*)d_in[ip];

    const int rows = out_size;                       // B*T = 8192
    int ir = (ip == 0) ? 1 : 0;
    for (int i = 0; i < n_in; i++)
        if (i != ip && in_sizes[i] == rows) { ir = i; break; }
    const float* rng = (const float*)d_in[ir];

    float* out = (float*)d_out;                      // output dtype: float32

    const long long pelems = (long long)in_sizes[ip];
    const int V = (int)(pelems / rows);              // 32000

    reset_counter_kernel<<<1, 1>>>();
    sampler_kernel<<<1184, 256>>>(p, rng, out, V, rows);
}